// round 7
// baseline (speedup 1.0000x reference)
#include <cuda_runtime.h>
#include <cstdint>

#define NN      100000
#define NE      1600000
#define HID     16
#define OUTD    40
#define QMAXF   255.0f

// ---------------------------------------------------------------------------
// Scratch (device globals — allocation is forbidden)
// ---------------------------------------------------------------------------
__device__ __align__(16) float g_ya[NN * HID];
__device__ __align__(16) float g_yb[NN * HID];
__device__ __align__(16) int2 g_ecv[NE];   // row-sorted (col, val-bits)
__device__ int   g_cnt[NN];
__device__ int   g_cur[NN];
__device__ int   g_off[NN + 1];
__device__ int   g_bsum[128];

// ---------------------------------------------------------------------------
// CSR build: clear -> hist -> scan1 -> scan3(folded base) -> scatter
// ---------------------------------------------------------------------------
__global__ void __launch_bounds__(256) k_clear() {
    int t = blockIdx.x * 256 + threadIdx.x;
    if (t < NN) g_cnt[t] = 0;
}

__global__ void __launch_bounds__(256) k_hist(const int* __restrict__ row) {
    int e = blockIdx.x * 256 + threadIdx.x;
    if (e < NE) atomicAdd(&g_cnt[__ldg(&row[e])], 1);
}

__global__ void __launch_bounds__(256) k_scan1() {
    int b = blockIdx.x, t = threadIdx.x;
    int base = b * 1024 + t * 4;
    int s = 0;
#pragma unroll
    for (int i = 0; i < 4; i++) { int idx = base + i; if (idx < NN) s += g_cnt[idx]; }
    __shared__ int sh[256];
    sh[t] = s; __syncthreads();
#pragma unroll
    for (int o = 128; o > 0; o >>= 1) {
        if (t < o) sh[t] += sh[t + o];
        __syncthreads();
    }
    if (t == 0) g_bsum[b] = sh[0];
}

__global__ void __launch_bounds__(256) k_scan3() {
    int b = blockIdx.x, t = threadIdx.x;
    int base = b * 1024 + t * 4;
    int c[4]; int tot = 0;
#pragma unroll
    for (int i = 0; i < 4; i++) {
        int idx = base + i;
        c[i] = (idx < NN) ? g_cnt[idx] : 0;
        tot += c[i];
    }
    __shared__ int sh[256];
    sh[t] = tot; __syncthreads();
#pragma unroll
    for (int o = 1; o < 256; o <<= 1) {
        int u = (t >= o) ? sh[t - o] : 0;
        __syncthreads();
        sh[t] += u;
        __syncthreads();
    }
    const int exclThread = sh[t] - tot;
    __syncthreads();

    sh[t] = (t < b) ? g_bsum[t] : 0;
    __syncthreads();
#pragma unroll
    for (int o = 128; o > 0; o >>= 1) {
        if (t < o) sh[t] += sh[t + o];
        __syncthreads();
    }
    int run = sh[0] + exclThread;
#pragma unroll
    for (int i = 0; i < 4; i++) {
        int idx = base + i;
        if (idx < NN) { g_off[idx] = run; g_cur[idx] = run; run += c[i]; }
    }
    if (b == 0 && t == 0) g_off[NN] = NE;
}

__global__ void __launch_bounds__(256) k_scatter(
    const int* __restrict__ row, const int* __restrict__ col,
    const float* __restrict__ vals)
{
    int e = blockIdx.x * 256 + threadIdx.x;
    if (e >= NE) return;
    int r = __ldg(&row[e]);
    int p = atomicAdd(&g_cur[r], 1);
    g_ecv[p] = make_int2(__ldg(&col[e]), __float_as_int(__ldg(&vals[e])));
}

// ---------------------------------------------------------------------------
// Layer 1: per-row (128-dim) qdq fused with x @ W1 -> y [N,16]. Warp per row.
// ---------------------------------------------------------------------------
template<int OFF, int V>
__device__ __forceinline__ void reduce_stage(float* acc, int lane) {
    const bool hi = (lane & OFF) != 0;
    float out[V];
#pragma unroll
    for (int m = 0; m < V; m++) {
        float keep = hi ? acc[m + V] : acc[m];
        float send = hi ? acc[m]     : acc[m + V];
        out[m] = keep + __shfl_xor_sync(0xffffffffu, send, OFF);
    }
#pragma unroll
    for (int m = 0; m < V; m++) acc[m] = out[m];
}

__global__ void __launch_bounds__(128) k_layer1(
    const float* __restrict__ x, const float* __restrict__ noise,
    const float* __restrict__ W1, float* __restrict__ y)
{
    const int lane   = threadIdx.x & 31;
    const int warpId = (blockIdx.x * (blockDim.x >> 5)) + (threadIdx.x >> 5);
    const int nWarp  = gridDim.x * (blockDim.x >> 5);

    float4 w[16];
    const float4* W4 = (const float4*)W1;
#pragma unroll
    for (int i = 0; i < 4; i++)
#pragma unroll
        for (int jj = 0; jj < 4; jj++)
            w[i * 4 + jj] = __ldg(&W4[(lane * 4 + i) * 4 + jj]);

    for (int r = warpId; r < NN; r += nWarp) {
        float4 xv = __ldg(&((const float4*)x)[r * 32 + lane]);
        float4 nv = __ldg(&((const float4*)noise)[r * 32 + lane]);
        float xa[4] = {xv.x, xv.y, xv.z, xv.w};
        float na[4] = {nv.x, nv.y, nv.z, nv.w};

        float mn = fminf(fminf(xa[0], xa[1]), fminf(xa[2], xa[3]));
        float mx = fmaxf(fmaxf(xa[0], xa[1]), fmaxf(xa[2], xa[3]));
#pragma unroll
        for (int off = 16; off > 0; off >>= 1) {
            mn = fminf(mn, __shfl_xor_sync(0xffffffffu, mn, off));
            mx = fmaxf(mx, __shfl_xor_sync(0xffffffffu, mx, off));
        }

        float dq[4];
        if (mx > mn) {
            float rs = QMAXF / (mx - mn);
#pragma unroll
            for (int i = 0; i < 4; i++) {
                float q = rintf((xa[i] - mn) * rs + na[i] - 0.5f);
                q = fminf(fmaxf(q, 0.f), QMAXF);
                dq[i] = q / rs + mn;
            }
        } else {
#pragma unroll
            for (int i = 0; i < 4; i++) dq[i] = mn;
        }

        float acc[16];
#pragma unroll
        for (int j = 0; j < 16; j++) acc[j] = 0.f;
#pragma unroll
        for (int i = 0; i < 4; i++) {
#pragma unroll
            for (int jj = 0; jj < 4; jj++) {
                float4 ww = w[i * 4 + jj];
                acc[jj * 4 + 0] = fmaf(dq[i], ww.x, acc[jj * 4 + 0]);
                acc[jj * 4 + 1] = fmaf(dq[i], ww.y, acc[jj * 4 + 1]);
                acc[jj * 4 + 2] = fmaf(dq[i], ww.z, acc[jj * 4 + 2]);
                acc[jj * 4 + 3] = fmaf(dq[i], ww.w, acc[jj * 4 + 3]);
            }
        }
        reduce_stage<16, 8>(acc, lane);
        reduce_stage<8, 4>(acc, lane);
        reduce_stage<4, 2>(acc, lane);
        reduce_stage<2, 1>(acc, lane);
        float s = acc[0] + __shfl_xor_sync(0xffffffffu, acc[0], 1);
        if ((lane & 1) == 0)
            y[r * 16 + ((lane >> 1) & 15)] = s;
    }
}

// ---------------------------------------------------------------------------
// CSR row-gather SpMM, lane-vectorized: half-warp per row organized as
// 4 edge-groups (g) x 4 dim-chunks (q). One LDG.128 gather serves 4 edges.
// Ws PADDED to 16*44 (zero pad) — inactive lanes (c>=10) still issue the
// shared loads; pad keeps them in-bounds (R6 crash fix).
//   EP=1: relu+qdq+@W(16x16) -> y    EP=2: relu+qdq -> y    EP=3: @W3 -> out
// ---------------------------------------------------------------------------
template<int EP>
__global__ void __launch_bounds__(256) k_spmm(
    const float* __restrict__ yin, const float* __restrict__ noise,
    const float* __restrict__ W, float* __restrict__ out)
{
    __shared__ __align__(16) float Ws[16 * 44];          // 704 (64-float pad)
    if (EP == 1) Ws[threadIdx.x] = W[threadIdx.x];
    if (EP == 3) {
        for (int i = threadIdx.x; i < 704; i += 256)
            Ws[i] = (i < 640) ? W[i] : 0.f;
    }
    if (EP != 2) __syncthreads();

    const int lane = threadIdx.x & 31;
    const int q    = lane & 3;            // dim chunk (dims q*4 .. q*4+3)
    const int g    = (lane >> 2) & 3;     // edge group
    const int h    = lane >> 4;           // half id
    const int r    = (blockIdx.x * 8 + (threadIdx.x >> 5)) * 2 + h;

    const int s = __ldg(&g_off[r]);
    const int e = __ldg(&g_off[r + 1]);
    const float4* y4 = (const float4*)yin;

    float4 acc  = make_float4(0.f, 0.f, 0.f, 0.f);
    float4 acc2 = make_float4(0.f, 0.f, 0.f, 0.f);

    int base = s;
    for (; base + 8 <= e; base += 8) {                 // 8 edges / iter
        int2 cv0 = __ldg(&g_ecv[base + g]);
        int2 cv1 = __ldg(&g_ecv[base + 4 + g]);
        float4 a = __ldg(&y4[cv0.x * 4 + q]);
        float4 b = __ldg(&y4[cv1.x * 4 + q]);
        float v0 = __int_as_float(cv0.y);
        float v1 = __int_as_float(cv1.y);
        acc.x  = fmaf(v0, a.x, acc.x);  acc.y  = fmaf(v0, a.y, acc.y);
        acc.z  = fmaf(v0, a.z, acc.z);  acc.w  = fmaf(v0, a.w, acc.w);
        acc2.x = fmaf(v1, b.x, acc2.x); acc2.y = fmaf(v1, b.y, acc2.y);
        acc2.z = fmaf(v1, b.z, acc2.z); acc2.w = fmaf(v1, b.w, acc2.w);
    }
    if (base + 4 <= e) {                               // 4-edge step
        int2 cv = __ldg(&g_ecv[base + g]);
        float4 a = __ldg(&y4[cv.x * 4 + q]);
        float v = __int_as_float(cv.y);
        acc.x = fmaf(v, a.x, acc.x); acc.y = fmaf(v, a.y, acc.y);
        acc.z = fmaf(v, a.z, acc.z); acc.w = fmaf(v, a.w, acc.w);
        base += 4;
    }
    if (base + g < e) {                                // tail (<4 edges)
        int2 cv = __ldg(&g_ecv[base + g]);
        float4 a = __ldg(&y4[cv.x * 4 + q]);
        float v = __int_as_float(cv.y);
        acc2.x = fmaf(v, a.x, acc2.x); acc2.y = fmaf(v, a.y, acc2.y);
        acc2.z = fmaf(v, a.z, acc2.z); acc2.w = fmaf(v, a.w, acc2.w);
    }
    acc.x += acc2.x; acc.y += acc2.y; acc.z += acc2.z; acc.w += acc2.w;

    // reduce over edge-groups (lane bits 2,3)
#pragma unroll
    for (int o = 4; o <= 8; o <<= 1) {
        acc.x += __shfl_xor_sync(0xffffffffu, acc.x, o);
        acc.y += __shfl_xor_sync(0xffffffffu, acc.y, o);
        acc.z += __shfl_xor_sync(0xffffffffu, acc.z, o);
        acc.w += __shfl_xor_sync(0xffffffffu, acc.w, o);
    }
    // every lane now holds z[r][q*4 .. q*4+3]

    if (EP == 3) {
        const int c = g * 4 + q;                       // out chunk (c<10 live)
        float4 a = make_float4(0.f, 0.f, 0.f, 0.f);
#pragma unroll
        for (int jq = 0; jq < 4; jq++) {
            int src = h * 16 + jq;                     // lane holding chunk jq
            float d0 = __shfl_sync(0xffffffffu, acc.x, src);
            float d1 = __shfl_sync(0xffffffffu, acc.y, src);
            float d2 = __shfl_sync(0xffffffffu, acc.z, src);
            float d3 = __shfl_sync(0xffffffffu, acc.w, src);
            float4 w0 = *(const float4*)&Ws[(jq * 4 + 0) * 40 + c * 4];
            float4 w1 = *(const float4*)&Ws[(jq * 4 + 1) * 40 + c * 4];
            float4 w2 = *(const float4*)&Ws[(jq * 4 + 2) * 40 + c * 4];
            float4 w3 = *(const float4*)&Ws[(jq * 4 + 3) * 40 + c * 4];
            a.x = fmaf(d0, w0.x, fmaf(d1, w1.x, fmaf(d2, w2.x, fmaf(d3, w3.x, a.x))));
            a.y = fmaf(d0, w0.y, fmaf(d1, w1.y, fmaf(d2, w2.y, fmaf(d3, w3.y, a.y))));
            a.z = fmaf(d0, w0.z, fmaf(d1, w1.z, fmaf(d2, w2.z, fmaf(d3, w3.z, a.z))));
            a.w = fmaf(d0, w0.w, fmaf(d1, w1.w, fmaf(d2, w2.w, fmaf(d3, w3.w, a.w))));
        }
        if (c < 10) ((float4*)(out + (size_t)r * 40))[c] = a;
    } else {
        float4 xr;
        xr.x = fmaxf(acc.x, 0.f); xr.y = fmaxf(acc.y, 0.f);
        xr.z = fmaxf(acc.z, 0.f); xr.w = fmaxf(acc.w, 0.f);
        float mn = fminf(fminf(xr.x, xr.y), fminf(xr.z, xr.w));
        float mx = fmaxf(fmaxf(xr.x, xr.y), fmaxf(xr.z, xr.w));
        mn = fminf(mn, __shfl_xor_sync(0xffffffffu, mn, 1));
        mx = fmaxf(mx, __shfl_xor_sync(0xffffffffu, mx, 1));
        mn = fminf(mn, __shfl_xor_sync(0xffffffffu, mn, 2));
        mx = fmaxf(mx, __shfl_xor_sync(0xffffffffu, mx, 2));

        float4 dq;
        if (mx > mn) {
            float rs = QMAXF / (mx - mn);
            float4 nz = __ldg(&((const float4*)noise)[r * 4 + q]);
            float q0 = fminf(fmaxf(rintf((xr.x - mn) * rs + nz.x - 0.5f), 0.f), QMAXF);
            float q1 = fminf(fmaxf(rintf((xr.y - mn) * rs + nz.y - 0.5f), 0.f), QMAXF);
            float q2 = fminf(fmaxf(rintf((xr.z - mn) * rs + nz.z - 0.5f), 0.f), QMAXF);
            float q3 = fminf(fmaxf(rintf((xr.w - mn) * rs + nz.w - 0.5f), 0.f), QMAXF);
            dq = make_float4(q0 / rs + mn, q1 / rs + mn, q2 / rs + mn, q3 / rs + mn);
        } else {
            dq = make_float4(mn, mn, mn, mn);
        }

        if (EP == 2) {
            if (g == 0) ((float4*)out)[r * 4 + q] = dq;
        } else {
            float4 a = make_float4(0.f, 0.f, 0.f, 0.f);
#pragma unroll
            for (int jq = 0; jq < 4; jq++) {
                int src = h * 16 + jq;
                float d0 = __shfl_sync(0xffffffffu, dq.x, src);
                float d1 = __shfl_sync(0xffffffffu, dq.y, src);
                float d2 = __shfl_sync(0xffffffffu, dq.z, src);
                float d3 = __shfl_sync(0xffffffffu, dq.w, src);
                float4 w0 = *(const float4*)&Ws[(jq * 4 + 0) * 16 + q * 4];
                float4 w1 = *(const float4*)&Ws[(jq * 4 + 1) * 16 + q * 4];
                float4 w2 = *(const float4*)&Ws[(jq * 4 + 2) * 16 + q * 4];
                float4 w3 = *(const float4*)&Ws[(jq * 4 + 3) * 16 + q * 4];
                a.x = fmaf(d0, w0.x, fmaf(d1, w1.x, fmaf(d2, w2.x, fmaf(d3, w3.x, a.x))));
                a.y = fmaf(d0, w0.y, fmaf(d1, w1.y, fmaf(d2, w2.y, fmaf(d3, w3.y, a.y))));
                a.z = fmaf(d0, w0.z, fmaf(d1, w1.z, fmaf(d2, w2.z, fmaf(d3, w3.z, a.z))));
                a.w = fmaf(d0, w0.w, fmaf(d1, w1.w, fmaf(d2, w2.w, fmaf(d3, w3.w, a.w))));
            }
            if (g == 0) ((float4*)out)[r * 4 + q] = a;
        }
    }
}

// ---------------------------------------------------------------------------
extern "C" void kernel_launch(void* const* d_in, const int* in_sizes, int n_in,
                              void* d_out, int out_size)
{
    const float* features = (const float*)d_in[0];
    const int*   row      = (const int*)  d_in[1];
    const int*   col      = (const int*)  d_in[2];
    const float* vals     = (const float*)d_in[3];
    const float* W1       = (const float*)d_in[4];
    const float* W2       = (const float*)d_in[5];
    const float* W3       = (const float*)d_in[6];
    const float* noise1   = (const float*)d_in[7];
    const float* noise2   = (const float*)d_in[8];
    const float* noise3   = (const float*)d_in[9];

    float *pya, *pyb;
    cudaGetSymbolAddress((void**)&pya, g_ya);
    cudaGetSymbolAddress((void**)&pyb, g_yb);

    const int nodeBlocks = (NN + 255) / 256;     // 391
    const int edgeBlocks = (NE + 255) / 256;     // 6250
    const int scanBlocks = (NN + 1023) / 1024;   // 98

    // CSR build
    k_clear  <<<nodeBlocks, 256>>>();
    k_hist   <<<edgeBlocks, 256>>>(row);
    k_scan1  <<<scanBlocks, 256>>>();
    k_scan3  <<<scanBlocks, 256>>>();
    k_scatter<<<edgeBlocks, 256>>>(row, col, vals);

    // Layer 1 dense front
    k_layer1<<<740, 128>>>(features, noise1, W1, pya);

    // SpMM pipeline (lane-vectorized half-warp per row)
    k_spmm<1><<<NN / 16, 256>>>(pya, noise2, W2, pyb);
    k_spmm<2><<<NN / 16, 256>>>(pyb, noise3, nullptr, pya);
    k_spmm<3><<<NN / 16, 256>>>(pya, nullptr, W3, (float*)d_out);
}

// round 8
// speedup vs baseline: 1.0312x; 1.0312x over previous
#include <cuda_runtime.h>
#include <cuda_fp16.h>
#include <cstdint>

#define NN      100000
#define NE      1600000
#define HID     16
#define OUTD    40
#define QMAXF   255.0f

// ---------------------------------------------------------------------------
// Scratch (device globals — allocation is forbidden)
// ---------------------------------------------------------------------------
__device__ __align__(16) __half g_yha[NN * HID];   // fp16 activations ping
__device__ __align__(16) __half g_yhb[NN * HID];   // fp16 activations pong
__device__ __align__(16) int2 g_ecv[NE];           // row-sorted (col, val-bits)
__device__ int   g_cnt[NN];
__device__ int   g_cur[NN];
__device__ int   g_off[NN + 1];
__device__ int   g_bsum[128];

// ---------------------------------------------------------------------------
// CSR build: clear -> hist -> scan1 -> scan3(folded base) -> scatter
// ---------------------------------------------------------------------------
__global__ void __launch_bounds__(256) k_clear() {
    int t = blockIdx.x * 256 + threadIdx.x;
    if (t < NN) g_cnt[t] = 0;
}

__global__ void __launch_bounds__(256) k_hist(const int* __restrict__ row) {
    int e = blockIdx.x * 256 + threadIdx.x;
    if (e < NE) atomicAdd(&g_cnt[__ldg(&row[e])], 1);
}

__global__ void __launch_bounds__(256) k_scan1() {
    int b = blockIdx.x, t = threadIdx.x;
    int base = b * 1024 + t * 4;
    int s = 0;
#pragma unroll
    for (int i = 0; i < 4; i++) { int idx = base + i; if (idx < NN) s += g_cnt[idx]; }
    __shared__ int sh[256];
    sh[t] = s; __syncthreads();
#pragma unroll
    for (int o = 128; o > 0; o >>= 1) {
        if (t < o) sh[t] += sh[t + o];
        __syncthreads();
    }
    if (t == 0) g_bsum[b] = sh[0];
}

__global__ void __launch_bounds__(256) k_scan3() {
    int b = blockIdx.x, t = threadIdx.x;
    int base = b * 1024 + t * 4;
    int c[4]; int tot = 0;
#pragma unroll
    for (int i = 0; i < 4; i++) {
        int idx = base + i;
        c[i] = (idx < NN) ? g_cnt[idx] : 0;
        tot += c[i];
    }
    __shared__ int sh[256];
    sh[t] = tot; __syncthreads();
#pragma unroll
    for (int o = 1; o < 256; o <<= 1) {
        int u = (t >= o) ? sh[t - o] : 0;
        __syncthreads();
        sh[t] += u;
        __syncthreads();
    }
    const int exclThread = sh[t] - tot;
    __syncthreads();

    sh[t] = (t < b) ? g_bsum[t] : 0;
    __syncthreads();
#pragma unroll
    for (int o = 128; o > 0; o >>= 1) {
        if (t < o) sh[t] += sh[t + o];
        __syncthreads();
    }
    int run = sh[0] + exclThread;
#pragma unroll
    for (int i = 0; i < 4; i++) {
        int idx = base + i;
        if (idx < NN) { g_off[idx] = run; g_cur[idx] = run; run += c[i]; }
    }
    if (b == 0 && t == 0) g_off[NN] = NE;
}

__global__ void __launch_bounds__(256) k_scatter(
    const int* __restrict__ row, const int* __restrict__ col,
    const float* __restrict__ vals)
{
    int e = blockIdx.x * 256 + threadIdx.x;
    if (e >= NE) return;
    int r = __ldg(&row[e]);
    int p = atomicAdd(&g_cur[r], 1);
    g_ecv[p] = make_int2(__ldg(&col[e]), __float_as_int(__ldg(&vals[e])));
}

// ---------------------------------------------------------------------------
// Layer 1: per-row (128-dim) qdq fused with x @ W1 -> y [N,16] fp16.
// Warp per row; W1 register-resident.
// ---------------------------------------------------------------------------
template<int OFF, int V>
__device__ __forceinline__ void reduce_stage(float* acc, int lane) {
    const bool hi = (lane & OFF) != 0;
    float out[V];
#pragma unroll
    for (int m = 0; m < V; m++) {
        float keep = hi ? acc[m + V] : acc[m];
        float send = hi ? acc[m]     : acc[m + V];
        out[m] = keep + __shfl_xor_sync(0xffffffffu, send, OFF);
    }
#pragma unroll
    for (int m = 0; m < V; m++) acc[m] = out[m];
}

__global__ void __launch_bounds__(128) k_layer1(
    const float* __restrict__ x, const float* __restrict__ noise,
    const float* __restrict__ W1, __half* __restrict__ y)
{
    const int lane   = threadIdx.x & 31;
    const int warpId = (blockIdx.x * (blockDim.x >> 5)) + (threadIdx.x >> 5);
    const int nWarp  = gridDim.x * (blockDim.x >> 5);

    float4 w[16];
    const float4* W4 = (const float4*)W1;
#pragma unroll
    for (int i = 0; i < 4; i++)
#pragma unroll
        for (int jj = 0; jj < 4; jj++)
            w[i * 4 + jj] = __ldg(&W4[(lane * 4 + i) * 4 + jj]);

    for (int r = warpId; r < NN; r += nWarp) {
        float4 xv = __ldg(&((const float4*)x)[r * 32 + lane]);
        float4 nv = __ldg(&((const float4*)noise)[r * 32 + lane]);
        float xa[4] = {xv.x, xv.y, xv.z, xv.w};
        float na[4] = {nv.x, nv.y, nv.z, nv.w};

        float mn = fminf(fminf(xa[0], xa[1]), fminf(xa[2], xa[3]));
        float mx = fmaxf(fmaxf(xa[0], xa[1]), fmaxf(xa[2], xa[3]));
#pragma unroll
        for (int off = 16; off > 0; off >>= 1) {
            mn = fminf(mn, __shfl_xor_sync(0xffffffffu, mn, off));
            mx = fmaxf(mx, __shfl_xor_sync(0xffffffffu, mx, off));
        }

        float dq[4];
        if (mx > mn) {
            float rs = QMAXF / (mx - mn);
#pragma unroll
            for (int i = 0; i < 4; i++) {
                float q = rintf((xa[i] - mn) * rs + na[i] - 0.5f);
                q = fminf(fmaxf(q, 0.f), QMAXF);
                dq[i] = q / rs + mn;
            }
        } else {
#pragma unroll
            for (int i = 0; i < 4; i++) dq[i] = mn;
        }

        float acc[16];
#pragma unroll
        for (int j = 0; j < 16; j++) acc[j] = 0.f;
#pragma unroll
        for (int i = 0; i < 4; i++) {
#pragma unroll
            for (int jj = 0; jj < 4; jj++) {
                float4 ww = w[i * 4 + jj];
                acc[jj * 4 + 0] = fmaf(dq[i], ww.x, acc[jj * 4 + 0]);
                acc[jj * 4 + 1] = fmaf(dq[i], ww.y, acc[jj * 4 + 1]);
                acc[jj * 4 + 2] = fmaf(dq[i], ww.z, acc[jj * 4 + 2]);
                acc[jj * 4 + 3] = fmaf(dq[i], ww.w, acc[jj * 4 + 3]);
            }
        }
        reduce_stage<16, 8>(acc, lane);
        reduce_stage<8, 4>(acc, lane);
        reduce_stage<4, 2>(acc, lane);
        reduce_stage<2, 1>(acc, lane);
        float s = acc[0] + __shfl_xor_sync(0xffffffffu, acc[0], 1);
        if ((lane & 1) == 0)
            y[r * 16 + ((lane >> 1) & 15)] = __float2half_rn(s);
    }
}

// ---------------------------------------------------------------------------
// CSR row-gather SpMM (R2 skeleton): half-warp (16 lanes = 16 dims) per row,
// 4 edges / iteration; y gathered as fp16 (1 sector per edge vs 2 for fp32).
// Accumulation fp32.
//   EP=1: relu+qdq+@W(16x16) -> y(fp16)
//   EP=2: relu+qdq           -> y(fp16)
//   EP=3: @W3(16x40)         -> out(fp32)
// Grid: 6250 blocks x 8 warps x 2 rows = 100000 rows.
// ---------------------------------------------------------------------------
template<int EP>
__global__ void __launch_bounds__(256) k_spmm(
    const __half* __restrict__ yin, const float* __restrict__ noise,
    const float* __restrict__ W, void* __restrict__ outv)
{
    __shared__ float Ws[16 * 40];
    if (EP == 1) Ws[threadIdx.x] = W[threadIdx.x];
    if (EP == 3) { for (int i = threadIdx.x; i < 640; i += 256) Ws[i] = W[i]; }
    if (EP != 2) __syncthreads();

    const int lane = threadIdx.x & 31;
    const int l    = lane & 15;                       // dim index
    const int r    = (blockIdx.x * 8 + (threadIdx.x >> 5)) * 2 + (lane >> 4);

    int       i = __ldg(&g_off[r]);
    const int e = __ldg(&g_off[r + 1]);
    float acc = 0.f;

    for (; i + 3 < e; i += 4) {
        int2 c0 = __ldg(&g_ecv[i]);
        int2 c1 = __ldg(&g_ecv[i + 1]);
        int2 c2 = __ldg(&g_ecv[i + 2]);
        int2 c3 = __ldg(&g_ecv[i + 3]);
        float y0 = __half2float(__ldg(&yin[c0.x * 16 + l]));
        float y1 = __half2float(__ldg(&yin[c1.x * 16 + l]));
        float y2 = __half2float(__ldg(&yin[c2.x * 16 + l]));
        float y3 = __half2float(__ldg(&yin[c3.x * 16 + l]));
        acc = fmaf(__int_as_float(c0.y), y0, acc);
        acc = fmaf(__int_as_float(c1.y), y1, acc);
        acc = fmaf(__int_as_float(c2.y), y2, acc);
        acc = fmaf(__int_as_float(c3.y), y3, acc);
    }
    for (; i < e; i++) {
        int2 cv = __ldg(&g_ecv[i]);
        acc = fmaf(__int_as_float(cv.y),
                   __half2float(__ldg(&yin[cv.x * 16 + l])), acc);
    }

    if (EP == 3) {
        float* out = (float*)outv;
        float a0 = 0.f, a1 = 0.f, a2 = 0.f;
#pragma unroll
        for (int j = 0; j < 16; j++) {
            float d = __shfl_sync(0xffffffffu, acc, (lane & 16) + j);
            a0 = fmaf(d, Ws[j * 40 + l], a0);
            a1 = fmaf(d, Ws[j * 40 + l + 16], a1);
            if (l < 8) a2 = fmaf(d, Ws[j * 40 + l + 32], a2);
        }
        out[r * 40 + l]      = a0;
        out[r * 40 + l + 16] = a1;
        if (l < 8) out[r * 40 + l + 32] = a2;
    } else {
        __half* out = (__half*)outv;
        float xr = fmaxf(acc, 0.f);
        float mn = xr, mx = xr;
#pragma unroll
        for (int o = 8; o > 0; o >>= 1) {
            mn = fminf(mn, __shfl_xor_sync(0xffffffffu, mn, o));
            mx = fmaxf(mx, __shfl_xor_sync(0xffffffffu, mx, o));
        }
        float dq;
        if (mx > mn) {
            float rs = QMAXF / (mx - mn);
            float nz = __ldg(&noise[r * 16 + l]);
            float q  = rintf((xr - mn) * rs + nz - 0.5f);
            q = fminf(fmaxf(q, 0.f), QMAXF);
            dq = q / rs + mn;
        } else dq = mn;

        if (EP == 2) {
            out[r * 16 + l] = __float2half_rn(dq);
        } else {
            float a = 0.f;
#pragma unroll
            for (int j = 0; j < 16; j++) {
                float d = __shfl_sync(0xffffffffu, dq, (lane & 16) + j);
                a = fmaf(d, Ws[j * 16 + l], a);
            }
            out[r * 16 + l] = __float2half_rn(a);
        }
    }
}

// ---------------------------------------------------------------------------
extern "C" void kernel_launch(void* const* d_in, const int* in_sizes, int n_in,
                              void* d_out, int out_size)
{
    const float* features = (const float*)d_in[0];
    const int*   row      = (const int*)  d_in[1];
    const int*   col      = (const int*)  d_in[2];
    const float* vals     = (const float*)d_in[3];
    const float* W1       = (const float*)d_in[4];
    const float* W2       = (const float*)d_in[5];
    const float* W3       = (const float*)d_in[6];
    const float* noise1   = (const float*)d_in[7];
    const float* noise2   = (const float*)d_in[8];
    const float* noise3   = (const float*)d_in[9];

    __half *pya, *pyb;
    cudaGetSymbolAddress((void**)&pya, g_yha);
    cudaGetSymbolAddress((void**)&pyb, g_yhb);

    const int nodeBlocks = (NN + 255) / 256;     // 391
    const int edgeBlocks = (NE + 255) / 256;     // 6250
    const int scanBlocks = (NN + 1023) / 1024;   // 98

    // CSR build
    k_clear  <<<nodeBlocks, 256>>>();
    k_hist   <<<edgeBlocks, 256>>>(row);
    k_scan1  <<<scanBlocks, 256>>>();
    k_scan3  <<<scanBlocks, 256>>>();
    k_scatter<<<edgeBlocks, 256>>>(row, col, vals);

    // Layer 1 dense front (fp16 output)
    k_layer1<<<740, 128>>>(features, noise1, W1, pya);

    // SpMM pipeline (fp16 gathers)
    k_spmm<1><<<NN / 16, 256>>>(pya, noise2, W2, pyb);
    k_spmm<2><<<NN / 16, 256>>>(pyb, noise3, nullptr, pya);
    k_spmm<3><<<NN / 16, 256>>>(pya, nullptr, W3, (float*)d_out);
}

// round 9
// speedup vs baseline: 1.0637x; 1.0315x over previous
#include <cuda_runtime.h>
#include <cstdint>

#define NN      100000
#define NE      1600000
#define HID     16
#define OUTD    40
#define QMAXF   255.0f

#define SPMM_BLOCKS 1184   // ~1 wave; 16 half-warps/block -> ~5.3 rows each

// ---------------------------------------------------------------------------
// Scratch (device globals — allocation is forbidden)
// ---------------------------------------------------------------------------
__device__ __align__(16) float g_ya[NN * HID];
__device__ __align__(16) float g_yb[NN * HID];
__device__ __align__(16) int2 g_ecv[NE];   // row-sorted (col, val-bits)
__device__ int   g_cnt[NN];
__device__ int   g_cur[NN];
__device__ int   g_off[NN + 1];
__device__ int   g_bsum[128];

// ---------------------------------------------------------------------------
// CSR build: clear -> hist -> scan1 -> scan3(folded base) -> scatter
// ---------------------------------------------------------------------------
__global__ void __launch_bounds__(256) k_clear() {
    int t = blockIdx.x * 256 + threadIdx.x;
    if (t < NN) g_cnt[t] = 0;
}

__global__ void __launch_bounds__(256) k_hist(const int* __restrict__ row) {
    int e = blockIdx.x * 256 + threadIdx.x;
    if (e < NE) atomicAdd(&g_cnt[__ldg(&row[e])], 1);
}

__global__ void __launch_bounds__(256) k_scan1() {
    int b = blockIdx.x, t = threadIdx.x;
    int base = b * 1024 + t * 4;
    int s = 0;
#pragma unroll
    for (int i = 0; i < 4; i++) { int idx = base + i; if (idx < NN) s += g_cnt[idx]; }
    __shared__ int sh[256];
    sh[t] = s; __syncthreads();
#pragma unroll
    for (int o = 128; o > 0; o >>= 1) {
        if (t < o) sh[t] += sh[t + o];
        __syncthreads();
    }
    if (t == 0) g_bsum[b] = sh[0];
}

__global__ void __launch_bounds__(256) k_scan3() {
    int b = blockIdx.x, t = threadIdx.x;
    int base = b * 1024 + t * 4;
    int c[4]; int tot = 0;
#pragma unroll
    for (int i = 0; i < 4; i++) {
        int idx = base + i;
        c[i] = (idx < NN) ? g_cnt[idx] : 0;
        tot += c[i];
    }
    __shared__ int sh[256];
    sh[t] = tot; __syncthreads();
#pragma unroll
    for (int o = 1; o < 256; o <<= 1) {
        int u = (t >= o) ? sh[t - o] : 0;
        __syncthreads();
        sh[t] += u;
        __syncthreads();
    }
    const int exclThread = sh[t] - tot;
    __syncthreads();

    sh[t] = (t < b) ? g_bsum[t] : 0;
    __syncthreads();
#pragma unroll
    for (int o = 128; o > 0; o >>= 1) {
        if (t < o) sh[t] += sh[t + o];
        __syncthreads();
    }
    int run = sh[0] + exclThread;
#pragma unroll
    for (int i = 0; i < 4; i++) {
        int idx = base + i;
        if (idx < NN) { g_off[idx] = run; g_cur[idx] = run; run += c[i]; }
    }
    if (b == 0 && t == 0) g_off[NN] = NE;
}

__global__ void __launch_bounds__(256) k_scatter(
    const int* __restrict__ row, const int* __restrict__ col,
    const float* __restrict__ vals)
{
    int e = blockIdx.x * 256 + threadIdx.x;
    if (e >= NE) return;
    int r = __ldg(&row[e]);
    int p = atomicAdd(&g_cur[r], 1);
    g_ecv[p] = make_int2(__ldg(&col[e]), __float_as_int(__ldg(&vals[e])));
}

// ---------------------------------------------------------------------------
// Layer 1: per-row (128-dim) qdq fused with x @ W1 -> y [N,16]. Warp per row.
// ---------------------------------------------------------------------------
template<int OFF, int V>
__device__ __forceinline__ void reduce_stage(float* acc, int lane) {
    const bool hi = (lane & OFF) != 0;
    float out[V];
#pragma unroll
    for (int m = 0; m < V; m++) {
        float keep = hi ? acc[m + V] : acc[m];
        float send = hi ? acc[m]     : acc[m + V];
        out[m] = keep + __shfl_xor_sync(0xffffffffu, send, OFF);
    }
#pragma unroll
    for (int m = 0; m < V; m++) acc[m] = out[m];
}

__global__ void __launch_bounds__(128) k_layer1(
    const float* __restrict__ x, const float* __restrict__ noise,
    const float* __restrict__ W1, float* __restrict__ y)
{
    const int lane   = threadIdx.x & 31;
    const int warpId = (blockIdx.x * (blockDim.x >> 5)) + (threadIdx.x >> 5);
    const int nWarp  = gridDim.x * (blockDim.x >> 5);

    float4 w[16];
    const float4* W4 = (const float4*)W1;
#pragma unroll
    for (int i = 0; i < 4; i++)
#pragma unroll
        for (int jj = 0; jj < 4; jj++)
            w[i * 4 + jj] = __ldg(&W4[(lane * 4 + i) * 4 + jj]);

    for (int r = warpId; r < NN; r += nWarp) {
        float4 xv = __ldg(&((const float4*)x)[r * 32 + lane]);
        float4 nv = __ldg(&((const float4*)noise)[r * 32 + lane]);
        float xa[4] = {xv.x, xv.y, xv.z, xv.w};
        float na[4] = {nv.x, nv.y, nv.z, nv.w};

        float mn = fminf(fminf(xa[0], xa[1]), fminf(xa[2], xa[3]));
        float mx = fmaxf(fmaxf(xa[0], xa[1]), fmaxf(xa[2], xa[3]));
#pragma unroll
        for (int off = 16; off > 0; off >>= 1) {
            mn = fminf(mn, __shfl_xor_sync(0xffffffffu, mn, off));
            mx = fmaxf(mx, __shfl_xor_sync(0xffffffffu, mx, off));
        }

        float dq[4];
        if (mx > mn) {
            float rs = QMAXF / (mx - mn);
#pragma unroll
            for (int i = 0; i < 4; i++) {
                float q = rintf((xa[i] - mn) * rs + na[i] - 0.5f);
                q = fminf(fmaxf(q, 0.f), QMAXF);
                dq[i] = q / rs + mn;
            }
        } else {
#pragma unroll
            for (int i = 0; i < 4; i++) dq[i] = mn;
        }

        float acc[16];
#pragma unroll
        for (int j = 0; j < 16; j++) acc[j] = 0.f;
#pragma unroll
        for (int i = 0; i < 4; i++) {
#pragma unroll
            for (int jj = 0; jj < 4; jj++) {
                float4 ww = w[i * 4 + jj];
                acc[jj * 4 + 0] = fmaf(dq[i], ww.x, acc[jj * 4 + 0]);
                acc[jj * 4 + 1] = fmaf(dq[i], ww.y, acc[jj * 4 + 1]);
                acc[jj * 4 + 2] = fmaf(dq[i], ww.z, acc[jj * 4 + 2]);
                acc[jj * 4 + 3] = fmaf(dq[i], ww.w, acc[jj * 4 + 3]);
            }
        }
        reduce_stage<16, 8>(acc, lane);
        reduce_stage<8, 4>(acc, lane);
        reduce_stage<4, 2>(acc, lane);
        reduce_stage<2, 1>(acc, lane);
        float s = acc[0] + __shfl_xor_sync(0xffffffffu, acc[0], 1);
        if ((lane & 1) == 0)
            y[r * 16 + ((lane >> 1) & 15)] = s;
    }
}

// ---------------------------------------------------------------------------
// CSR row-gather SpMM: half-warp (16 lanes = 16 dims) per row, 4-edge unroll
// (R2 skeleton), GRID-STRIDE over rows: ~1 wave of blocks, each half-warp
// serially processes ~5 rows -> averages Poisson row-length imbalance and
// keeps the gather pipeline warm across rows.
//   EP=1: relu+qdq+@W(16x16) -> y    EP=2: relu+qdq -> y    EP=3: @W3 -> out
// ---------------------------------------------------------------------------
template<int EP>
__global__ void __launch_bounds__(256) k_spmm(
    const float* __restrict__ yin, const float* __restrict__ noise,
    const float* __restrict__ W, float* __restrict__ out)
{
    __shared__ float Ws[16 * 40];
    if (EP == 1) Ws[threadIdx.x] = W[threadIdx.x];
    if (EP == 3) { for (int i = threadIdx.x; i < 640; i += 256) Ws[i] = W[i]; }
    if (EP != 2) __syncthreads();

    const int lane  = threadIdx.x & 31;
    const int l     = lane & 15;                       // dim index
    const int half0 = (blockIdx.x * 8 + (threadIdx.x >> 5)) * 2 + (lane >> 4);
    const int nHalf = SPMM_BLOCKS * 16;

    for (int r = half0; r < NN; r += nHalf) {
        int       i = __ldg(&g_off[r]);
        const int e = __ldg(&g_off[r + 1]);
        float acc = 0.f;

        for (; i + 3 < e; i += 4) {
            int2 c0 = __ldg(&g_ecv[i]);
            int2 c1 = __ldg(&g_ecv[i + 1]);
            int2 c2 = __ldg(&g_ecv[i + 2]);
            int2 c3 = __ldg(&g_ecv[i + 3]);
            float y0 = __ldg(&yin[c0.x * 16 + l]);
            float y1 = __ldg(&yin[c1.x * 16 + l]);
            float y2 = __ldg(&yin[c2.x * 16 + l]);
            float y3 = __ldg(&yin[c3.x * 16 + l]);
            acc = fmaf(__int_as_float(c0.y), y0, acc);
            acc = fmaf(__int_as_float(c1.y), y1, acc);
            acc = fmaf(__int_as_float(c2.y), y2, acc);
            acc = fmaf(__int_as_float(c3.y), y3, acc);
        }
        for (; i < e; i++) {
            int2 cv = __ldg(&g_ecv[i]);
            acc = fmaf(__int_as_float(cv.y), __ldg(&yin[cv.x * 16 + l]), acc);
        }

        if (EP == 3) {
            float a0 = 0.f, a1 = 0.f, a2 = 0.f;
#pragma unroll
            for (int j = 0; j < 16; j++) {
                float d = __shfl_sync(0xffffffffu, acc, (lane & 16) + j);
                a0 = fmaf(d, Ws[j * 40 + l], a0);
                a1 = fmaf(d, Ws[j * 40 + l + 16], a1);
                if (l < 8) a2 = fmaf(d, Ws[j * 40 + l + 32], a2);
            }
            out[r * 40 + l]      = a0;
            out[r * 40 + l + 16] = a1;
            if (l < 8) out[r * 40 + l + 32] = a2;
        } else {
            float xr = fmaxf(acc, 0.f);
            float mn = xr, mx = xr;
#pragma unroll
            for (int o = 8; o > 0; o >>= 1) {
                mn = fminf(mn, __shfl_xor_sync(0xffffffffu, mn, o));
                mx = fmaxf(mx, __shfl_xor_sync(0xffffffffu, mx, o));
            }
            float dq;
            if (mx > mn) {
                float rs = QMAXF / (mx - mn);
                float nz = __ldg(&noise[r * 16 + l]);
                float q  = rintf((xr - mn) * rs + nz - 0.5f);
                q = fminf(fmaxf(q, 0.f), QMAXF);
                dq = q / rs + mn;
            } else dq = mn;

            if (EP == 2) {
                out[r * 16 + l] = dq;
            } else {
                float a = 0.f;
#pragma unroll
                for (int j = 0; j < 16; j++) {
                    float d = __shfl_sync(0xffffffffu, dq, (lane & 16) + j);
                    a = fmaf(d, Ws[j * 16 + l], a);
                }
                out[r * 16 + l] = a;
            }
        }
    }
}

// ---------------------------------------------------------------------------
extern "C" void kernel_launch(void* const* d_in, const int* in_sizes, int n_in,
                              void* d_out, int out_size)
{
    const float* features = (const float*)d_in[0];
    const int*   row      = (const int*)  d_in[1];
    const int*   col      = (const int*)  d_in[2];
    const float* vals     = (const float*)d_in[3];
    const float* W1       = (const float*)d_in[4];
    const float* W2       = (const float*)d_in[5];
    const float* W3       = (const float*)d_in[6];
    const float* noise1   = (const float*)d_in[7];
    const float* noise2   = (const float*)d_in[8];
    const float* noise3   = (const float*)d_in[9];

    float *pya, *pyb;
    cudaGetSymbolAddress((void**)&pya, g_ya);
    cudaGetSymbolAddress((void**)&pyb, g_yb);

    const int nodeBlocks = (NN + 255) / 256;     // 391
    const int edgeBlocks = (NE + 255) / 256;     // 6250
    const int scanBlocks = (NN + 1023) / 1024;   // 98

    // CSR build
    k_clear  <<<nodeBlocks, 256>>>();
    k_hist   <<<edgeBlocks, 256>>>(row);
    k_scan1  <<<scanBlocks, 256>>>();
    k_scan3  <<<scanBlocks, 256>>>();
    k_scatter<<<edgeBlocks, 256>>>(row, col, vals);

    // Layer 1 dense front
    k_layer1<<<740, 128>>>(features, noise1, W1, pya);

    // SpMM pipeline (grid-stride row batching, ~1 wave)
    k_spmm<1><<<SPMM_BLOCKS, 256>>>(pya, noise2, W2, pyb);
    k_spmm<2><<<SPMM_BLOCKS, 256>>>(pyb, noise3, nullptr, pya);
    k_spmm<3><<<SPMM_BLOCKS, 256>>>(pya, nullptr, W3, (float*)d_out);
}